// round 16
// baseline (speedup 1.0000x reference)
#include <cuda_runtime.h>
#include <cstdint>
#include <math.h>

#define NMAX  100000
#define FIN   128
#define C1    16
#define C2    8

// Device state (zero-init at load; g_deg restored to zero each call in phase 2)
__device__ __align__(16) int    g_deg [NMAX];
__device__ __align__(16) float  g_y   [NMAX];
__device__ __align__(16) float2 g_nd1 [NMAX];   // {dinv*y, dinv}
__device__ __align__(16) float2 g_acc [NMAX];   // layer-1 accum (self-seeded)
__device__ __align__(16) float  g_dinv[NMAX];
__device__ __align__(16) float  g_p   [NMAX];   // dinv^2 * acc.x
__device__ __align__(16) float  g_gg  [NMAX];   // layer-2 accum (self-seeded)
__device__ __align__(16) float  g_sf  [NMAX];
__device__ __align__(16) float  g_z   [NMAX];
__device__ unsigned g_bar_cnt;                  // barrier arrival counter
__device__ unsigned g_bar_gen;                  // barrier generation

// fp32 reductions, no return
__device__ __forceinline__ void red_add_v2(float2* addr, float a, float b) {
    asm volatile(
        "{\n\t.reg .u64 ga;\n\tcvta.to.global.u64 ga, %0;\n\t"
        "red.global.add.v2.f32 [ga], {%1, %2};\n\t}"
        :: "l"(addr), "f"(a), "f"(b) : "memory");
}
__device__ __forceinline__ void red_add_f(float* addr, float a) {
    asm volatile(
        "{\n\t.reg .u64 ga;\n\tcvta.to.global.u64 ga, %0;\n\t"
        "red.global.add.f32 [ga], %1;\n\t}"
        :: "l"(addr), "f"(a) : "memory");
}

// Software grid barrier (all nb blocks co-resident via occupancy-bounded launch)
__device__ __forceinline__ void gbar(unsigned nb) {
    __threadfence();
    __syncthreads();
    if (threadIdx.x == 0) {
        volatile unsigned* genp = &g_bar_gen;
        unsigned gen = *genp;
        unsigned t = atomicAdd(&g_bar_cnt, 1u);
        if (t == nb - 1u) {
            g_bar_cnt = 0u;
            __threadfence();
            *genp = gen + 1u;
        } else {
            while (*genp == gen) __nanosleep(32);
        }
    }
    __syncthreads();
    __threadfence();
}

// 6 blocks/SM -> <=42 regs: keeps the L2-bound phases at high warp concurrency
__global__ __launch_bounds__(256, 6) void k_all(
    const float* __restrict__ x,
    const int* __restrict__ src, const int* __restrict__ dst,
    const int* __restrict__ pe,
    const float* __restrict__ W1, const float* __restrict__ b1,
    const float* __restrict__ W2, const float* __restrict__ b2,
    const float* __restrict__ Wl, const float* __restrict__ bl,
    float* __restrict__ out,
    int n, int E, int P, unsigned nb)
{
    __shared__ float sm_m[FIN];
    __shared__ float sm_ab[2];

    int tid = threadIdx.x;
    // Per-block weight fold (redundant across blocks, trivial cost)
    if (tid < FIN) {
        float acc = 0.0f;
#pragma unroll
        for (int j = 0; j < C1; j++) {
            float inner = 0.0f;
#pragma unroll
            for (int k = 0; k < C2; k++) inner += W2[j * C2 + k] * Wl[k];
            acc += W1[tid * C1 + j] * inner;
        }
        sm_m[tid] = acc;
    }
    if (tid == 0) {
        float alpha = 0.0f, beta = bl[0];
#pragma unroll
        for (int k = 0; k < C2; k++) {
            float ck = 0.0f;
#pragma unroll
            for (int j = 0; j < C1; j++) ck += b1[j] * W2[j * C2 + k];
            alpha += ck * Wl[k];
            beta  += b2[k] * Wl[k];
        }
        sm_ab[0] = alpha;
        sm_ab[1] = beta;
    }
    __syncthreads();

    int gtid    = blockIdx.x * 256 + tid;
    int gstride = gridDim.x * 256;

    // ---- Phase 1: degree atomics (L2) + y = x·m (DRAM) — overlapping ----
    int nq = E >> 2;
    for (int t = gtid; t < nq; t += gstride) {
        int4 d4 = reinterpret_cast<const int4*>(dst)[t];
        atomicAdd(&g_deg[d4.x], 1);
        atomicAdd(&g_deg[d4.y], 1);
        atomicAdd(&g_deg[d4.z], 1);
        atomicAdd(&g_deg[d4.w], 1);
    }
    for (int e = (nq << 2) + gtid; e < E; e += gstride)
        atomicAdd(&g_deg[dst[e]], 1);

    {
        int warpId = gtid >> 5, lane = gtid & 31, nwarp = gstride >> 5;
        float4 mv = reinterpret_cast<const float4*>(sm_m)[lane];
        for (int i = warpId; i < n; i += nwarp) {
            float4 xv = reinterpret_cast<const float4*>(x)[i * 32 + lane];
            float p = xv.x * mv.x + xv.y * mv.y + xv.z * mv.z + xv.w * mv.w;
#pragma unroll
            for (int o = 16; o; o >>= 1) p += __shfl_xor_sync(0xffffffffu, p, o);
            if (lane == 0) g_y[i] = p;
        }
    }
    gbar(nb);

    // ---- Phase 2: nd = {dinv*y, dinv}; seed acc; reset deg ----
    for (int i = gtid; i < n; i += gstride) {
        float dv = rsqrtf((float)g_deg[i] + 1.0f);
        float2 nd = make_float2(dv * g_y[i], dv);
        g_dinv[i] = dv;
        g_nd1[i]  = nd;
        g_acc[i]  = nd;
        g_deg[i]  = 0;
    }
    gbar(nb);

    // ---- Phase 3: agg layer 1 ----
    for (int e = gtid; e < E; e += gstride) {
        float2 nd = g_nd1[src[e]];
        red_add_v2(&g_acc[dst[e]], nd.x, nd.y);
    }
    gbar(nb);

    // ---- Phase 4: finalize L1, seed L2 ----
    for (int i = gtid; i < n; i += gstride) {
        float2 a = g_acc[i];
        float dv = g_dinv[i];
        float p  = dv * dv * a.x;
        g_p[i]  = p;
        g_gg[i] = p;
        g_sf[i] = dv * a.y;
    }
    gbar(nb);

    // ---- Phase 5: agg layer 2 ----
    for (int e = gtid; e < E; e += gstride)
        red_add_f(&g_gg[dst[e]], g_p[src[e]]);
    gbar(nb);

    // ---- Phase 6: head ----
    for (int i = gtid; i < n; i += gstride) {
        float acc = g_dinv[i] * g_gg[i] + sm_ab[0] * g_sf[i] + sm_ab[1];
        g_z[i] = 1.0f / (1.0f + expf(-acc));
    }
    gbar(nb);

    // ---- Phase 7: pair predictions ----
    for (int p = gtid; p < P; p += gstride) {
        int2 ab = reinterpret_cast<const int2*>(pe)[p];
        out[p] = g_z[ab.x] * g_z[ab.y];
    }
}

extern "C" void kernel_launch(void* const* d_in, const int* in_sizes, int n_in,
                              void* d_out, int out_size) {
    const float* x   = (const float*)d_in[0];
    const int*   ei  = (const int*)d_in[1];
    const int*   pe  = (const int*)d_in[2];
    const float* W1  = (const float*)d_in[3];
    const float* b1  = (const float*)d_in[4];
    const float* W2  = (const float*)d_in[5];
    const float* b2  = (const float*)d_in[6];
    const float* Wl  = (const float*)d_in[7];
    const float* bl  = (const float*)d_in[8];
    float* out = (float*)d_out;

    int n = in_sizes[0] / FIN;
    int E = in_sizes[1] / 2;
    int P = in_sizes[2] / 2;

    const int* src = ei;
    const int* dst = ei + E;

    int dev = 0, sms = 0, bpsm = 0;
    cudaGetDevice(&dev);
    cudaDeviceGetAttribute(&sms, cudaDevAttrMultiProcessorCount, dev);
    cudaOccupancyMaxActiveBlocksPerMultiprocessor(&bpsm, k_all, 256, 0);
    if (bpsm < 1) bpsm = 1;
    unsigned grid = (unsigned)(sms * bpsm);
    if (grid < 1u) grid = 1u;

    k_all<<<grid, 256>>>(x, src, dst, pe, W1, b1, W2, b2, Wl, bl, out,
                         n, E, P, grid);
}

// round 17
// speedup vs baseline: 1.3021x; 1.3021x over previous
#include <cuda_runtime.h>
#include <cstdint>
#include <math.h>

#define NMAX  100000
#define FIN   128
#define C1    16
#define C2    8

// Device state (zero-init at load; g_deg re-zeroed in k_nd each call)
__device__ __align__(16) int    g_deg [NMAX];
__device__ __align__(16) float  g_y   [NMAX];
__device__ __align__(16) float2 g_nd1 [NMAX];   // {dinv*y, dinv}
__device__ __align__(16) float2 g_acc [NMAX];   // layer-1 accum (self-seeded)
__device__ __align__(16) float  g_dinv[NMAX];
__device__ __align__(16) float  g_p   [NMAX];   // dinv^2 * acc.x
__device__ __align__(16) float  g_gg  [NMAX];   // layer-2 accum (self-seeded)
__device__ __align__(16) float  g_sf  [NMAX];
__device__ __align__(16) float  g_z   [NMAX];
__device__ float g_alpha, g_beta;

// fp32 reductions, no return
__device__ __forceinline__ void red_add_v2(float2* addr, float a, float b) {
    asm volatile(
        "{\n\t.reg .u64 ga;\n\tcvta.to.global.u64 ga, %0;\n\t"
        "red.global.add.v2.f32 [ga], {%1, %2};\n\t}"
        :: "l"(addr), "f"(a), "f"(b) : "memory");
}
__device__ __forceinline__ void red_add_f(float* addr, float a) {
    asm volatile(
        "{\n\t.reg .u64 ga;\n\tcvta.to.global.u64 ga, %0;\n\t"
        "red.global.add.f32 [ga], %1;\n\t}"
        :: "l"(addr), "f"(a) : "memory");
}

// ---------------------------------------------------------------------------
// K1: fused degree atomics (L2-bound) + y = x·m (DRAM-bound) — independent
// outputs, no ordering needed; DRAM streaming hides under the atomic pass.
__global__ __launch_bounds__(256) void k_degy(const int* __restrict__ dst,
                                              const float* __restrict__ x,
                                              const float* __restrict__ W1,
                                              const float* __restrict__ W2,
                                              const float* __restrict__ Wl,
                                              int n, int E) {
    __shared__ float sm_m[FIN];
    int tid = threadIdx.x;
    if (tid < FIN) {
        float acc = 0.0f;
#pragma unroll
        for (int j = 0; j < C1; j++) {
            float inner = 0.0f;
#pragma unroll
            for (int k = 0; k < C2; k++) inner += W2[j * C2 + k] * Wl[k];
            acc += W1[tid * C1 + j] * inner;
        }
        sm_m[tid] = acc;
    }
    __syncthreads();

    int gtid    = blockIdx.x * 256 + tid;
    int gstride = gridDim.x * 256;

    // degree atomics, 4 edges/thread
    int nq = E >> 2;
    for (int t = gtid; t < nq; t += gstride) {
        int4 d4 = reinterpret_cast<const int4*>(dst)[t];
        atomicAdd(&g_deg[d4.x], 1);
        atomicAdd(&g_deg[d4.y], 1);
        atomicAdd(&g_deg[d4.z], 1);
        atomicAdd(&g_deg[d4.w], 1);
    }
    for (int e = (nq << 2) + gtid; e < E; e += gstride)
        atomicAdd(&g_deg[dst[e]], 1);

    // y = x·m, warp per node (grid-stride over nodes)
    {
        int warpId = gtid >> 5, lane = gtid & 31, nwarp = gstride >> 5;
        float4 mv = reinterpret_cast<const float4*>(sm_m)[lane];
        for (int i = warpId; i < n; i += nwarp) {
            float4 xv = reinterpret_cast<const float4*>(x)[i * 32 + lane];
            float p = xv.x * mv.x + xv.y * mv.y + xv.z * mv.z + xv.w * mv.w;
#pragma unroll
            for (int o = 16; o; o >>= 1) p += __shfl_xor_sync(0xffffffffu, p, o);
            if (lane == 0) g_y[i] = p;
        }
    }
}

// K2: nd = {dinv*y, dinv}; seed acc; reset deg; block 0 publishes alpha/beta
__global__ void k_nd(const float* __restrict__ b1, const float* __restrict__ b2,
                     const float* __restrict__ W2, const float* __restrict__ Wl,
                     const float* __restrict__ bl, int n) {
    if (blockIdx.x == 0 && threadIdx.x == 0) {
        float alpha = 0.0f, beta = bl[0];
#pragma unroll
        for (int k = 0; k < C2; k++) {
            float ck = 0.0f;
#pragma unroll
            for (int j = 0; j < C1; j++) ck += b1[j] * W2[j * C2 + k];
            alpha += ck * Wl[k];
            beta  += b2[k] * Wl[k];
        }
        g_alpha = alpha;
        g_beta  = beta;
    }
    int i = blockIdx.x * blockDim.x + threadIdx.x;
    if (i >= n) return;
    float dv = rsqrtf((float)g_deg[i] + 1.0f);
    float2 nd = make_float2(dv * g_y[i], dv);
    g_dinv[i] = dv;
    g_nd1[i]  = nd;
    g_acc[i]  = nd;      // self-loop seed
    g_deg[i]  = 0;       // restore zero invariant for next call
}

// K3: agg layer 1 — 1 edge/thread: acc[d] += {ys[s], dinv[s]}
__global__ void k_agg1(const int* __restrict__ src,
                       const int* __restrict__ dst, int E) {
    int e = blockIdx.x * blockDim.x + threadIdx.x;
    if (e >= E) return;
    float2 nd = g_nd1[src[e]];
    red_add_v2(&g_acc[dst[e]], nd.x, nd.y);
}

// K4: finalize layer 1 + seed layer 2
__global__ void k_mid(int n) {
    int i = blockIdx.x * blockDim.x + threadIdx.x;
    if (i >= n) return;
    float2 a = g_acc[i];
    float dv = g_dinv[i];
    float p  = dv * dv * a.x;
    g_p[i]  = p;
    g_gg[i] = p;
    g_sf[i] = dv * a.y;
}

// K5: agg layer 2 — 1 edge/thread: gg[d] += p[s]
__global__ void k_agg2(const int* __restrict__ src,
                       const int* __restrict__ dst, int E) {
    int e = blockIdx.x * blockDim.x + threadIdx.x;
    if (e >= E) return;
    red_add_f(&g_gg[dst[e]], g_p[src[e]]);
}

// K6: z = sigmoid(dinv*gg + alpha*sfull + beta)
__global__ void k_head(int n) {
    int i = blockIdx.x * blockDim.x + threadIdx.x;
    if (i >= n) return;
    float acc = g_dinv[i] * g_gg[i] + g_alpha * g_sf[i] + g_beta;
    g_z[i] = 1.0f / (1.0f + expf(-acc));
}

// K7: pred[p] = z[pe[p,0]] * z[pe[p,1]]
__global__ void k_pred(const int* __restrict__ pe,
                       float* __restrict__ out, int P) {
    int p = blockIdx.x * blockDim.x + threadIdx.x;
    if (p >= P) return;
    int2 ab = reinterpret_cast<const int2*>(pe)[p];
    out[p] = g_z[ab.x] * g_z[ab.y];
}

extern "C" void kernel_launch(void* const* d_in, const int* in_sizes, int n_in,
                              void* d_out, int out_size) {
    const float* x   = (const float*)d_in[0];
    const int*   ei  = (const int*)d_in[1];
    const int*   pe  = (const int*)d_in[2];
    const float* W1  = (const float*)d_in[3];
    const float* b1  = (const float*)d_in[4];
    const float* W2  = (const float*)d_in[5];
    const float* b2  = (const float*)d_in[6];
    const float* Wl  = (const float*)d_in[7];
    const float* bl  = (const float*)d_in[8];
    float* out = (float*)d_out;

    int n = in_sizes[0] / FIN;
    int E = in_sizes[1] / 2;
    int P = in_sizes[2] / 2;

    const int* src = ei;
    const int* dst = ei + E;

    const int T = 256;

    k_degy<<<(E / 4 + T - 1) / T, T>>>(dst, x, W1, W2, Wl, n, E);
    k_nd  <<<(n + T - 1) / T, T>>>(b1, b2, W2, Wl, bl, n);
    k_agg1<<<(E + T - 1) / T, T>>>(src, dst, E);
    k_mid <<<(n + T - 1) / T, T>>>(n);
    k_agg2<<<(E + T - 1) / T, T>>>(src, dst, E);
    k_head<<<(n + T - 1) / T, T>>>(n);
    k_pred<<<(P + T - 1) / T, T>>>(pe, out, P);
}